// round 11
// baseline (speedup 1.0000x reference)
#include <cuda_runtime.h>
#include <cuda_bf16.h>
#include <cstdint>
#include <cstring>

// ---------------------------------------------------------------------------
// Net_autoencpsdhigh — round 11: skin = 128p x 96n, 256 thr, cp.async, 2/SM.
//   k_front  : prep(640) ∪ dk_partial(256) ∪ sw-split(320)
//   k_mid    : dk_combine(96) ∪ repack2(240)
//   k_detail : outp = (dk @ DPSD)*std+mean (HMMA, pipelined); dsq
//   k_skin   : outp += LBS skinned (HMMA, cp.async, 2 blocks/SM); L1 + loss
// ---------------------------------------------------------------------------

#define Bn    64
#define Pn    12273
#define Jn    80
#define MOTn  94
#define NKEY  340
#define NKEYP 384
#define NCOLS (Pn * 3)     // 36819
#define DKCH  64
#define SWTOT (96 * 128 * 80)

// ---- scratch ----------------------------------------------------------------
__device__ float         g_A[Bn * Jn * 12];
__device__ float         g_dkp[DKCH * 4 * 16 * NKEY];
__device__ __nv_bfloat16 g_dk_hi[Bn * NKEYP];
__device__ __nv_bfloat16 g_dk_lo[Bn * NKEYP];
__device__ __align__(16) __nv_bfloat16 g_Ac_hi[768 * 80];
__device__ __align__(16) __nv_bfloat16 g_Ac_lo[768 * 80];
__device__ __align__(16) __nv_bfloat16 g_sw_hi[SWTOT];
__device__ __align__(16) __nv_bfloat16 g_sw_lo[SWTOT];
__device__ float         g_l1, g_dsq;
__device__ unsigned      g_tick = 0;

// ---- f32x2 helpers ------------------------------------------------------------
__device__ __forceinline__ unsigned long long pack2(float a, float b) {
    unsigned long long r;
    asm("mov.b64 %0, {%1, %2};" : "=l"(r) : "f"(a), "f"(b));
    return r;
}
__device__ __forceinline__ void unpack2(unsigned long long v, float& a, float& b) {
    asm("mov.b64 {%0, %1}, %2;" : "=f"(a), "=f"(b) : "l"(v));
}
__device__ __forceinline__ void fma2(unsigned long long& d,
                                     unsigned long long a, unsigned long long b) {
    asm("fma.rn.f32x2 %0, %1, %2, %0;" : "+l"(d) : "l"(a), "l"(b));
}

// ---- HMMA / async helpers ------------------------------------------------------
__device__ __forceinline__ uint32_t smem_u32(const void* p) {
    uint32_t a;
    asm("{ .reg .u64 t; cvta.to.shared.u64 t, %1; cvt.u32.u64 %0, t; }"
        : "=r"(a) : "l"(p));
    return a;
}
__device__ __forceinline__ void cpasync16(uint32_t dst, const void* gsrc) {
    asm volatile("{ .reg .u64 g; cvta.to.global.u64 g, %1; "
                 "cp.async.ca.shared.global [%0], [g], 16; }"
                 :: "r"(dst), "l"(gsrc));
}
#define CPASYNC_WAIT() \
    asm volatile("cp.async.commit_group;\ncp.async.wait_group 0;" ::: "memory")

__device__ __forceinline__ void ldsm4(uint32_t* r, uint32_t addr) {
    asm volatile("ldmatrix.sync.aligned.m8n8.x4.shared.b16 {%0,%1,%2,%3}, [%4];"
                 : "=r"(r[0]), "=r"(r[1]), "=r"(r[2]), "=r"(r[3]) : "r"(addr));
}
__device__ __forceinline__ void ldsm4t(uint32_t* r, uint32_t addr) {
    asm volatile("ldmatrix.sync.aligned.m8n8.x4.trans.shared.b16 {%0,%1,%2,%3}, [%4];"
                 : "=r"(r[0]), "=r"(r[1]), "=r"(r[2]), "=r"(r[3]) : "r"(addr));
}
__device__ __forceinline__ void mma_bf16(float* c, const uint32_t* a,
                                         uint32_t b0, uint32_t b1) {
    asm volatile(
        "mma.sync.aligned.m16n8k16.row.col.f32.bf16.bf16.f32 "
        "{%0,%1,%2,%3}, {%4,%5,%6,%7}, {%8,%9}, {%0,%1,%2,%3};"
        : "+f"(c[0]), "+f"(c[1]), "+f"(c[2]), "+f"(c[3])
        : "r"(a[0]), "r"(a[1]), "r"(a[2]), "r"(a[3]), "r"(b0), "r"(b1));
}
__device__ __forceinline__ void mma3(float* c, const uint32_t* ah, const uint32_t* al,
                                     uint32_t bh0, uint32_t bh1,
                                     uint32_t bl0, uint32_t bl1) {
    mma_bf16(c, ah, bh0, bh1);
    mma_bf16(c, ah, bl0, bl1);
    mma_bf16(c, al, bh0, bh1);
}
__device__ __forceinline__ uint32_t pack2bf(__nv_bfloat16 a, __nv_bfloat16 b) {
    __nv_bfloat162 t = __halves2bfloat162(a, b);
    uint32_t r; memcpy(&r, &t, 4); return r;
}
__device__ __forceinline__ void split_bf(float v, __nv_bfloat16& h, __nv_bfloat16& l) {
    h = __float2bfloat16(v);
    l = __float2bfloat16(v - __bfloat162float(h));
}

// ---------------------------------------------------------------------------
// prep body: 384 threads, per (b, 8-joint tile).
__device__ void prep_body(float* sm, int bid,
                          const float* __restrict__ tmtemp, const float* __restrict__ mwl,
                          const float* __restrict__ query,  const float* __restrict__ W1,
                          const float* __restrict__ b1,     const float* __restrict__ W2,
                          const float* __restrict__ b2,
                          const float* __restrict__ cps, const float* __restrict__ cpm,
                          const float* __restrict__ cts, const float* __restrict__ ctm)
{
    float* tm_s  = sm;
    float* W1_s  = tm_s  + 94 * 64;
    float* mw_s  = W1_s  + 67 * 128;
    float* h_s   = mw_s  + 8 * 94;
    float* hid_s = h_s   + 8 * 68;
    float* pr_s  = hid_s + 8 * 128;
    float* W2_s  = pr_s  + 48;
    float* b1_s  = W2_s  + 768;

    const int tid = threadIdx.x;
    const int b   = bid / 10;
    const int l0  = (bid - b * 10) * 8;

    if (bid == 0 && tid == 0) { g_l1 = 0.f; g_dsq = 0.f; }

    for (int i = tid; i < 94 * 64; i += 384)  tm_s[i] = tmtemp[b * 6016 + i];
    for (int i = tid; i < 67 * 128; i += 384) W1_s[i] = W1[i];
    for (int i = tid; i < 768; i += 384)      W2_s[i] = W2[i];
    if (tid < 128) b1_s[tid] = b1[tid];
    for (int i = tid; i < 8 * 94; i += 384) {
        int ll = i / 94, jj = i - ll * 94;
        mw_s[i] = fmaxf(mwl[(l0 + ll) * 94 + jj], 0.f);
    }
    if (tid < 24) {
        int ll = tid / 3, x = tid - ll * 3;
        h_s[ll * 68 + x] = query[((b * 80) + l0 + ll) * 3 + x];
    }
    __syncthreads();

    for (int idx = tid; idx < 512; idx += 384) {
        int ll = idx >> 6, k = idx & 63;
        float s = 0.f;
        #pragma unroll 2
        for (int jm = 0; jm < 94; jm++)
            s = fmaf(mw_s[ll * 94 + jm], tm_s[jm * 64 + k], s);
        h_s[ll * 68 + 3 + k] = s;
    }
    __syncthreads();

    if (tid < 256) {
        const int h = tid & 127, lg = tid >> 7;
        float a0 = b1_s[h], a1 = a0, a2 = a0, a3 = a0;
        const float* h0 = h_s + (lg * 4 + 0) * 68;
        const float* h1 = h_s + (lg * 4 + 1) * 68;
        const float* h2 = h_s + (lg * 4 + 2) * 68;
        const float* h3 = h_s + (lg * 4 + 3) * 68;
        #pragma unroll 1
        for (int i = 0; i < 67; i++) {
            float wv = W1_s[i * 128 + h];
            a0 = fmaf(h0[i], wv, a0);
            a1 = fmaf(h1[i], wv, a1);
            a2 = fmaf(h2[i], wv, a2);
            a3 = fmaf(h3[i], wv, a3);
        }
        hid_s[(lg * 4 + 0) * 128 + h] = fmaxf(a0, 0.f);
        hid_s[(lg * 4 + 1) * 128 + h] = fmaxf(a1, 0.f);
        hid_s[(lg * 4 + 2) * 128 + h] = fmaxf(a2, 0.f);
        hid_s[(lg * 4 + 3) * 128 + h] = fmaxf(a3, 0.f);
    }
    __syncthreads();

    if (tid < 192) {
        int pid = tid >> 2, l4 = tid & 3;
        int ll = pid / 6, o = pid - ll * 6;
        float s = 0.f;
        const float* hp = hid_s + ll * 128 + l4 * 32;
        #pragma unroll
        for (int u = 0; u < 32; u++)
            s = fmaf(hp[u], W2_s[(l4 * 32 + u) * 6 + o], s);
        s += __shfl_down_sync(0xffffffffu, s, 2, 4);
        s += __shfl_down_sync(0xffffffffu, s, 1, 4);
        if (l4 == 0) pr_s[ll * 6 + o] = s + __ldg(&b2[o]);
    }
    __syncthreads();

    if (tid < 8) {
        const int ll = tid, gl = l0 + ll;
        const float DEG = 0.017453292519943295f;
        float px = fmaf(pr_s[ll * 6 + 0], cps[0], cpm[0]) * DEG;
        float py = fmaf(pr_s[ll * 6 + 1], cps[1], cpm[1]) * DEG;
        float pz = fmaf(pr_s[ll * 6 + 2], cps[2], cpm[2]) * DEG;
        float qx = h_s[ll * 68 + 0], qy = h_s[ll * 68 + 1], qz = h_s[ll * 68 + 2];
        float t0 = (qx + pr_s[ll * 6 + 3]) * cts[0] + ctm[0];
        float t1 = (qy + pr_s[ll * 6 + 4]) * cts[1] + ctm[1];
        float t2 = (qz + pr_s[ll * 6 + 5]) * cts[2] + ctm[2];
        float sx, cx, sy, cy, sz, cz;
        sincosf(px, &sx, &cx);
        sincosf(py, &sy, &cy);
        sincosf(pz, &sz, &cz);
        float* A = g_A + ((b * 80) + gl) * 12;
        A[0] = cz * cy; A[1] = cz * sy * sx - sz * cx; A[2] = cz * sy * cx + sz * sx;
        A[3] = sz * cy; A[4] = sz * sy * sx + cz * cx; A[5] = sz * sy * cx - cz * sx;
        A[6] = -sy;     A[7] = cy * sx;                A[8] = cy * cx;
        A[9] = t0; A[10] = t1; A[11] = t2;
    }
}

// ---------------------------------------------------------------------------
// dk_partial body: 384 threads (340 = m), per (94-col chunk, 16-b group).
__device__ void dkp_body(float2* tm2_s, int rid,
                         const float* __restrict__ tmtemp, const float* __restrict__ Wd)
{
    const int tid = threadIdx.x;
    const int c = rid >> 2, g = rid & 3;
    const int i0 = c * 94;
    for (int i = tid; i < 8 * 94; i += 384) {
        int bb2 = i / 94, ii = i - bb2 * 94;
        int b0 = g * 16 + bb2 * 2;
        tm2_s[i] = make_float2(tmtemp[b0 * 6016 + i0 + ii],
                               tmtemp[(b0 + 1) * 6016 + i0 + ii]);
    }
    __syncthreads();
    if (tid < NKEY) {
        unsigned long long acc[8];
        #pragma unroll
        for (int q = 0; q < 8; q++) acc[q] = 0ull;
        const unsigned long long* tp = (const unsigned long long*)tm2_s;
        const float* wp = Wd + (long long)i0 * NKEY + tid;
        for (int ii = 0; ii < 92; ii += 4) {
            float w0 = wp[(ii + 0) * NKEY];
            float w1 = wp[(ii + 1) * NKEY];
            float w2 = wp[(ii + 2) * NKEY];
            float w3 = wp[(ii + 3) * NKEY];
            unsigned long long p0 = pack2(w0, w0), p1 = pack2(w1, w1);
            unsigned long long p2 = pack2(w2, w2), p3 = pack2(w3, w3);
            #pragma unroll
            for (int q = 0; q < 8; q++) fma2(acc[q], tp[q * 94 + ii + 0], p0);
            #pragma unroll
            for (int q = 0; q < 8; q++) fma2(acc[q], tp[q * 94 + ii + 1], p1);
            #pragma unroll
            for (int q = 0; q < 8; q++) fma2(acc[q], tp[q * 94 + ii + 2], p2);
            #pragma unroll
            for (int q = 0; q < 8; q++) fma2(acc[q], tp[q * 94 + ii + 3], p3);
        }
        {
            float w0 = wp[92 * NKEY], w1 = wp[93 * NKEY];
            unsigned long long p0 = pack2(w0, w0), p1 = pack2(w1, w1);
            #pragma unroll
            for (int q = 0; q < 8; q++) fma2(acc[q], tp[q * 94 + 92], p0);
            #pragma unroll
            for (int q = 0; q < 8; q++) fma2(acc[q], tp[q * 94 + 93], p1);
        }
        float* outp = g_dkp + ((c * 4 + g) * 16) * NKEY + tid;
        #pragma unroll
        for (int q = 0; q < 8; q++) {
            float v0, v1; unpack2(acc[q], v0, v1);
            outp[(2 * q) * NKEY]     = v0;
            outp[(2 * q + 1) * NKEY] = v1;
        }
    }
}

// ---------------------------------------------------------------------------
// k_front: prep (640) ∪ dk_partial (256) ∪ sw-split (320). 384 thr, 71.4KB.
__global__ void __launch_bounds__(384)
k_front(const float* __restrict__ tmtemp, const float* __restrict__ mwl,
        const float* __restrict__ query,  const float* __restrict__ W1,
        const float* __restrict__ b1,     const float* __restrict__ W2,
        const float* __restrict__ b2,
        const float* __restrict__ cps, const float* __restrict__ cpm,
        const float* __restrict__ cts, const float* __restrict__ ctm,
        const float* __restrict__ Wd, const float* __restrict__ skinw)
{
    extern __shared__ float smf[];
    const int bid = blockIdx.x;
    if (bid < 640) {
        prep_body(smf, bid, tmtemp, mwl, query, W1, b1, W2, b2, cps, cpm, cts, ctm);
    } else if (bid < 896) {
        dkp_body((float2*)smf, bid - 640, tmtemp, Wd);
    } else {
        const int base = (bid - 896) * 384 * 8 + threadIdx.x;
        #pragma unroll
        for (int q = 0; q < 8; q++) {
            int idx = base + q * 384;
            if (idx < SWTOT) {
                float v = (idx < Pn * 80) ? skinw[idx] : 0.f;
                __nv_bfloat16 h, l;
                split_bf(v, h, l);
                g_sw_hi[idx] = h;
                g_sw_lo[idx] = l;
            }
        }
    }
}

// ---------------------------------------------------------------------------
// k_mid: dk_combine (96 blocks) ∪ repack2 (240 blocks). 256 thr.
__global__ void k_mid(const float* __restrict__ bd)
{
    const int bid = blockIdx.x;
    const int tid = threadIdx.x;
    if (bid < 96) {
        int idx = bid * 256 + tid;
        if (idx >= Bn * NKEYP) return;
        int b = idx / NKEYP, m = idx - b * NKEYP;
        float v = 0.f;
        if (m < NKEY) {
            v = bd[m];
            int gg = b >> 4, bb = b & 15;
            const float* base = g_dkp + (gg * 16 + bb) * NKEY + m;
            const long long S = 64LL * NKEY;
            float a0 = 0.f, a1 = 0.f, a2 = 0.f, a3 = 0.f;
            float a4 = 0.f, a5 = 0.f, a6 = 0.f, a7 = 0.f;
            #pragma unroll
            for (int cc = 0; cc < DKCH; cc += 8) {
                a0 += base[(cc + 0) * S];
                a1 += base[(cc + 1) * S];
                a2 += base[(cc + 2) * S];
                a3 += base[(cc + 3) * S];
                a4 += base[(cc + 4) * S];
                a5 += base[(cc + 5) * S];
                a6 += base[(cc + 6) * S];
                a7 += base[(cc + 7) * S];
            }
            v += ((a0 + a1) + (a2 + a3)) + ((a4 + a5) + (a6 + a7));
        }
        __nv_bfloat16 h, l;
        split_bf(v, h, l);
        g_dk_hi[idx] = h;
        g_dk_lo[idx] = l;
    } else {
        int idx = (bid - 96) * 256 + tid;
        if (idx >= 768 * 80) return;
        int n = idx / 80, j = idx - n * 80;
        int b = n / 12, q = n - b * 12;
        float v = g_A[(b * 80 + j) * 12 + q];
        __nv_bfloat16 h, l;
        split_bf(v, h, l);
        g_Ac_hi[idx] = h;
        g_Ac_lo[idx] = l;
    }
}

// ---------------------------------------------------------------------------
// k_detail_hmma: grid 288 c-tiles (128 cols), 256 threads, pipelined staging.
#define DTA_HI  0
#define DTA_LO  17408
#define DTB_HI  34816
#define DTB_LO  44032
#define DT_SMEM 53248

__global__ void __launch_bounds__(256)
k_detail_hmma(const float* __restrict__ DPSD,
              const float* __restrict__ sstd, const float* __restrict__ smean,
              float* __restrict__ outp)
{
    extern __shared__ __align__(16) char smem[];
    const uint32_t sb = smem_u32(smem);
    __shared__ float red[8];

    const int tid = threadIdx.x, lane = tid & 31, wid = tid >> 5;
    const int c0 = blockIdx.x * 128;
    const int wm = wid & 3, wn = wid >> 2;

    float acc[2][4][4];
    #pragma unroll
    for (int mf = 0; mf < 2; mf++)
        #pragma unroll
        for (int nf = 0; nf < 4; nf++)
            #pragma unroll
            for (int r = 0; r < 4; r++) acc[mf][nf][r] = 0.f;
    float dsq = 0.f;

    const int aKr = (lane & 7) + ((lane & 16) ? 8 : 0);
    const int aCc = wm * 32 + ((lane & 8) ? 8 : 0);
    const int bRow = wn * 32 + (lane & 7) + ((lane & 16) ? 8 : 0);
    const int bKc  = ((lane & 8) ? 8 : 0);

    const int cp = tid & 63, mrb = tid >> 6;
    const int myc = c0 + 2 * cp;
    const bool ok0 = myc < NCOLS, ok1 = myc + 1 < NCOLS;

    float pv0[16], pv1[16];
    #pragma unroll
    for (int q = 0; q < 16; q++) {
        int m = q * 4 + mrb;
        bool mv = m < NKEY;
        pv0[q] = (mv && ok0) ? DPSD[(long long)m * NCOLS + myc] : 0.f;
        pv1[q] = (mv && ok1) ? DPSD[(long long)m * NCOLS + myc + 1] : 0.f;
    }

    for (int ch = 0; ch < 6; ch++) {
        __syncthreads();
        #pragma unroll
        for (int q = 0; q < 16; q++) {
            int mr = q * 4 + mrb;
            float v0 = pv0[q], v1 = pv1[q];
            dsq = fmaf(v0, v0, fmaf(v1, v1, dsq));
            __nv_bfloat16 h0, l0, h1, l1;
            split_bf(v0, h0, l0); split_bf(v1, h1, l1);
            *(uint32_t*)(smem + DTA_HI + (mr * 136 + 2 * cp) * 2) = pack2bf(h0, h1);
            *(uint32_t*)(smem + DTA_LO + (mr * 136 + 2 * cp) * 2) = pack2bf(l0, l1);
        }
        const int m0 = ch * 64;
        #pragma unroll 2
        for (int q = 0; q < 8; q++) {
            int flat = q * 256 + tid;
            int bbq = flat >> 5, kp = flat & 31;
            uint32_t hv, lv;
            memcpy(&hv, g_dk_hi + bbq * NKEYP + m0 + 2 * kp, 4);
            memcpy(&lv, g_dk_lo + bbq * NKEYP + m0 + 2 * kp, 4);
            *(uint32_t*)(smem + DTB_HI + (bbq * 72 + 2 * kp) * 2) = hv;
            *(uint32_t*)(smem + DTB_LO + (bbq * 72 + 2 * kp) * 2) = lv;
        }
        __syncthreads();

        if (ch < 5) {
            const int mn0 = (ch + 1) * 64;
            #pragma unroll
            for (int q = 0; q < 16; q++) {
                int m = mn0 + q * 4 + mrb;
                bool mv = m < NKEY;
                pv0[q] = (mv && ok0) ? DPSD[(long long)m * NCOLS + myc] : 0.f;
                pv1[q] = (mv && ok1) ? DPSD[(long long)m * NCOLS + myc + 1] : 0.f;
            }
        }

        #pragma unroll
        for (int kk = 0; kk < 4; kk++) {
            uint32_t ah[2][4], al[2][4], bh[2][4], bl[2][4];
            uint32_t ao = (uint32_t)(((kk * 16 + aKr) * 136 + aCc) * 2);
            ldsm4t(ah[0], sb + DTA_HI + ao);
            ldsm4t(ah[1], sb + DTA_HI + ao + 32);
            ldsm4t(al[0], sb + DTA_LO + ao);
            ldsm4t(al[1], sb + DTA_LO + ao + 32);
            uint32_t bo = (uint32_t)((bRow * 72 + kk * 16 + bKc) * 2);
            ldsm4(bh[0], sb + DTB_HI + bo);
            ldsm4(bh[1], sb + DTB_HI + bo + 16 * 72 * 2);
            ldsm4(bl[0], sb + DTB_LO + bo);
            ldsm4(bl[1], sb + DTB_LO + bo + 16 * 72 * 2);
            #pragma unroll
            for (int mf = 0; mf < 2; mf++)
                #pragma unroll
                for (int nf = 0; nf < 4; nf++) {
                    int ng = nf >> 1, pr = (nf & 1) * 2;
                    mma3(acc[mf][nf], ah[mf], al[mf],
                         bh[ng][pr], bh[ng][pr + 1], bl[ng][pr], bl[ng][pr + 1]);
                }
        }
    }

    __syncthreads();
    float* Cs = (float*)smem;                    // [128][68]
    #pragma unroll
    for (int mf = 0; mf < 2; mf++)
        #pragma unroll
        for (int nf = 0; nf < 4; nf++) {
            int r  = wm * 32 + mf * 16 + (lane >> 2);
            int cb = wn * 32 + nf * 8 + (lane & 3) * 2;
            *(float2*)(Cs + r * 68 + cb)       = make_float2(acc[mf][nf][0], acc[mf][nf][1]);
            *(float2*)(Cs + (r + 8) * 68 + cb) = make_float2(acc[mf][nf][2], acc[mf][nf][3]);
        }
    __syncthreads();

    const float s0 = sstd[0], s1 = sstd[1], s2 = sstd[2];
    const float u0 = smean[0], u1 = smean[1], u2 = smean[2];
    #pragma unroll 2
    for (int q = 0; q < 32; q++) {
        int flat = q * 256 + tid;
        int cc = flat & 127, bb = flat >> 7;
        int ci = c0 + cc;
        if (ci < NCOLS) {
            int x = ci % 3;
            float sv = (x == 0) ? s0 : (x == 1) ? s1 : s2;
            float uv = (x == 0) ? u0 : (x == 1) ? u1 : u2;
            outp[(long long)bb * NCOLS + ci] = fmaf(Cs[cc * 68 + bb], sv, uv);
        }
    }

    #pragma unroll
    for (int off = 16; off; off >>= 1)
        dsq += __shfl_down_sync(0xffffffffu, dsq, off);
    if (lane == 0) red[wid] = dsq;
    __syncthreads();
    if (tid == 0) {
        float tdq = 0.f;
        #pragma unroll
        for (int w = 0; w < 8; w++) tdq += red[w];
        atomicAdd(&g_dsq, tdq);
    }
}

// ---------------------------------------------------------------------------
// k_skin_hmma: grid (96 p-tiles of 128, 8 b-groups of 8), 256 threads, 2/SM.
// C[p 128][n 96] = sw[p][80] @ Aco[n][80]^T via cp.async hi/lo tiles.
#define SKA_HI  0
#define SKA_LO  22528
#define SKB_HI  45056
#define SKB_LO  61952
#define SK_REST 78848
#define SK_SMEM 80896

__global__ void __launch_bounds__(256, 2)
k_skin_hmma(const float* __restrict__ rest,
            const float* __restrict__ inpc, float* __restrict__ out,
            float* __restrict__ outp)
{
    extern __shared__ __align__(16) char smem[];
    const uint32_t sb = smem_u32(smem);
    float4* rest4 = (float4*)(smem + SK_REST);
    __shared__ float red[8];

    const int tid = threadIdx.x, lane = tid & 31, wid = tid >> 5;
    const int p0 = blockIdx.x * 128;
    const int bg = blockIdx.y;                 // 8 batches per block
    const int wm = wid & 3, wn = wid >> 2;     // 4 m-quadrants x 2 n-groups(48)

    // stage A (sw hi/lo 128 rows) + B (Aco hi/lo 96 rows) via cp.async 16B
    #pragma unroll 2
    for (int i = tid; i < 1280; i += 256) {    // 128 rows x 10 chunks
        int row = i / 10, c = i - (i / 10) * 10;
        long long soff = (long long)(p0 + row) * 160 + c * 16;
        uint32_t doff = (uint32_t)(row * 176 + c * 16);
        cpasync16(sb + SKA_HI + doff, (const char*)g_sw_hi + soff);
        cpasync16(sb + SKA_LO + doff, (const char*)g_sw_lo + soff);
    }
    #pragma unroll 2
    for (int i = tid; i < 960; i += 256) {     // 96 rows x 10 chunks
        int row = i / 10, c = i - (i / 10) * 10;
        long long soff = (long long)(bg * 96 + row) * 160 + c * 16;
        uint32_t doff = (uint32_t)(row * 176 + c * 16);
        cpasync16(sb + SKB_HI + doff, (const char*)g_Ac_hi + soff);
        cpasync16(sb + SKB_LO + doff, (const char*)g_Ac_lo + soff);
    }
    if (tid < 128) {
        float4 r = make_float4(0.f, 0.f, 0.f, 1.f);
        if (p0 + tid < Pn) {
            r.x = rest[(p0 + tid) * 3 + 0];
            r.y = rest[(p0 + tid) * 3 + 1];
            r.z = rest[(p0 + tid) * 3 + 2];
        }
        rest4[tid] = r;
    }
    CPASYNC_WAIT();
    __syncthreads();

    float acc[2][6][4];
    #pragma unroll
    for (int mf = 0; mf < 2; mf++)
        #pragma unroll
        for (int nf = 0; nf < 6; nf++)
            #pragma unroll
            for (int r = 0; r < 4; r++) acc[mf][nf][r] = 0.f;

    const int aRow = wm * 32 + (lane & 7) + ((lane & 8) ? 8 : 0);
    const int aKc  = ((lane & 16) ? 8 : 0);
    const int bRow = wn * 48 + (lane & 7) + ((lane & 16) ? 8 : 0);
    const int bKc  = ((lane & 8) ? 8 : 0);

    #pragma unroll
    for (int kk = 0; kk < 5; kk++) {
        uint32_t ah[2][4], al[2][4];
        uint32_t ao = (uint32_t)((aRow * 88 + kk * 16 + aKc) * 2);
        ldsm4(ah[0], sb + SKA_HI + ao);
        ldsm4(ah[1], sb + SKA_HI + ao + 16 * 88 * 2);
        ldsm4(al[0], sb + SKA_LO + ao);
        ldsm4(al[1], sb + SKA_LO + ao + 16 * 88 * 2);
        #pragma unroll
        for (int ng = 0; ng < 3; ng++) {
            uint32_t bh4[4], bl4[4];
            uint32_t bo = (uint32_t)(((bRow + ng * 16) * 88 + kk * 16 + bKc) * 2);
            ldsm4(bh4, sb + SKB_HI + bo);
            ldsm4(bl4, sb + SKB_LO + bo);
            #pragma unroll
            for (int mf = 0; mf < 2; mf++) {
                mma3(acc[mf][ng * 2 + 0], ah[mf], al[mf],
                     bh4[0], bh4[1], bl4[0], bl4[1]);
                mma3(acc[mf][ng * 2 + 1], ah[mf], al[mf],
                     bh4[2], bh4[3], bl4[2], bl4[3]);
            }
        }
    }

    // stage C transposed: Cs[n][p], row pad 132 (fits in staging region)
    __syncthreads();
    float* Cs = (float*)smem;                  // [96][132]
    #pragma unroll
    for (int mf = 0; mf < 2; mf++)
        #pragma unroll
        for (int nf = 0; nf < 6; nf++) {
            int r  = wm * 32 + mf * 16 + (lane >> 2);
            int cb = wn * 48 + nf * 8 + (lane & 3) * 2;
            Cs[cb * 132 + r]           = acc[mf][nf][0];
            Cs[(cb + 1) * 132 + r]     = acc[mf][nf][1];
            Cs[cb * 132 + r + 8]       = acc[mf][nf][2];
            Cs[(cb + 1) * 132 + r + 8] = acc[mf][nf][3];
        }
    __syncthreads();

    float l1 = 0.f;
    #pragma unroll
    for (int q = 0; q < 4; q++) {
        int flat = q * 256 + tid;              // 128 p * 8 bl
        int p = flat & 127, bl = flat >> 7;
        float4 r = rest4[p];
        const float* cp = Cs + (bl * 12) * 132 + p;
        float m0 = cp[0],        m1 = cp[132],      m2 = cp[2 * 132];
        float m3 = cp[3 * 132],  m4 = cp[4 * 132],  m5 = cp[5 * 132];
        float m6 = cp[6 * 132],  m7 = cp[7 * 132],  m8 = cp[8 * 132];
        float m9 = cp[9 * 132],  mA = cp[10 * 132], mB = cp[11 * 132];
        if (p0 + p < Pn) {
            long long base = (long long)(bg * 8 + bl) * NCOLS + (p0 + p) * 3;
            float o0 = outp[base]     + fmaf(m0, r.x, fmaf(m1, r.y, fmaf(m2, r.z, m9)));
            float o1 = outp[base + 1] + fmaf(m3, r.x, fmaf(m4, r.y, fmaf(m5, r.z, mA)));
            float o2 = outp[base + 2] + fmaf(m6, r.x, fmaf(m7, r.y, fmaf(m8, r.z, mB)));
            outp[base]     = o0;
            outp[base + 1] = o1;
            outp[base + 2] = o2;
            l1 += fabsf(inpc[base]     - o0);
            l1 += fabsf(inpc[base + 1] - o1);
            l1 += fabsf(inpc[base + 2] - o2);
        }
    }

    #pragma unroll
    for (int off = 16; off; off >>= 1)
        l1 += __shfl_down_sync(0xffffffffu, l1, off);
    if (lane == 0) red[wid] = l1;
    __syncthreads();
    if (tid == 0) {
        float tl1 = 0.f;
        #pragma unroll
        for (int w = 0; w < 8; w++) tl1 += red[w];
        atomicAdd(&g_l1, tl1);
        __threadfence();
        unsigned t = atomicAdd(&g_tick, 1u);
        if (t == gridDim.x * gridDim.y - 1) {
            g_tick = 0;
            float fl1 = atomicAdd(&g_l1, 0.f);
            float fdq = atomicAdd(&g_dsq, 0.f);
            out[0] = fl1 * (1.f / (64.f * 12273.f * 3.f))
                   + 1e-4f * fdq * (1.f / (340.f * 12273.f * 3.f));
        }
    }
}

// ---------------------------------------------------------------------------
extern "C" void kernel_launch(void* const* d_in, const int* in_sizes, int n_in,
                              void* d_out, int out_size)
{
    const float* inpc   = (const float*)d_in[0];
    const float* rest   = (const float*)d_in[2];
    const float* skinw  = (const float*)d_in[3];
    const float* mwl    = (const float*)d_in[4];
    const float* query  = (const float*)d_in[5];
    const float* cps    = (const float*)d_in[6];
    const float* cpm    = (const float*)d_in[7];
    const float* cts    = (const float*)d_in[8];
    const float* ctm    = (const float*)d_in[9];
    const float* W1     = (const float*)d_in[10];
    const float* b1     = (const float*)d_in[11];
    const float* W2     = (const float*)d_in[12];
    const float* b2     = (const float*)d_in[13];
    const float* tmtemp = (const float*)d_in[14];
    const float* Wd     = (const float*)d_in[15];
    const float* bd     = (const float*)d_in[16];
    const float* DPSD   = (const float*)d_in[17];
    const float* sstd   = (const float*)d_in[18];
    const float* smean  = (const float*)d_in[19];

    float* out  = (float*)d_out;
    float* outp = out + 1;   // out[0] = loss, out[1:] = out_pc [B,P,3]

    const int front_smem = (94 * 64 + 67 * 128 + 8 * 94 + 8 * 68 + 8 * 128 + 48
                            + 768 + 128) * 4;   // 71424
    cudaFuncSetAttribute(k_front, cudaFuncAttributeMaxDynamicSharedMemorySize, front_smem);
    cudaFuncSetAttribute(k_skin_hmma, cudaFuncAttributeMaxDynamicSharedMemorySize, SK_SMEM);
    cudaFuncSetAttribute(k_detail_hmma, cudaFuncAttributeMaxDynamicSharedMemorySize, DT_SMEM);

    k_front<<<1216, 384, front_smem>>>(tmtemp, mwl, query, W1, b1, W2, b2,
                                       cps, cpm, cts, ctm, Wd, skinw);
    k_mid<<<336, 256>>>(bd);
    k_detail_hmma<<<288, 256, DT_SMEM>>>(DPSD, sstd, smean, outp);
    k_skin_hmma<<<dim3(96, 8), 256, SK_SMEM>>>(rest, inpc, out, outp);  // 4th: profiled
}